// round 1
// baseline (speedup 1.0000x reference)
#include <cuda_runtime.h>
#include <mma.h>

using namespace nvcuda;

#define BB   2
#define SS   2048
#define DD   1024
#define HH   16
#define DH   64
#define LDS  72   // smem row stride (floats): 288B = 9*32B -> 16B-aligned rows, legal wmma ldm

// Scratch (allocation-free rule: __device__ globals)
__device__ float g_q[BB * HH * SS * DH];
__device__ float g_k[BB * HH * SS * DH];
__device__ float g_v[BB * HH * SS * DH];
__device__ float g_ctx[BB * SS * DD];

using FragA  = wmma::fragment<wmma::matrix_a, 16, 16, 8, wmma::precision::tf32, wmma::row_major>;
using FragBr = wmma::fragment<wmma::matrix_b, 16, 16, 8, wmma::precision::tf32, wmma::row_major>;
using FragBc = wmma::fragment<wmma::matrix_b, 16, 16, 8, wmma::precision::tf32, wmma::col_major>;
using FragC  = wmma::fragment<wmma::accumulator, 16, 16, 8, float>;

__device__ __forceinline__ float tf32r(float x) { return wmma::__float_to_tf32(x); }

// ---------------------------------------------------------------------------
// 64x64 output tile GEMM:  out = A[4096,1024] @ W[1024,1024] + bias
// head_layout=1: store to [B,H,S,DH] split-head layout; else plain [M,N].
// 128 threads (4 warps), each warp computes a 16x64 strip.
// ---------------------------------------------------------------------------
__device__ __forceinline__ void gemm64x64(const float* __restrict__ A,
                                          const float* __restrict__ W,
                                          const float* __restrict__ bias,
                                          float* __restrict__ out,
                                          int head_layout)
{
    __shared__ float As[64][40];
    __shared__ float Ws[32][LDS];
    __shared__ float Cs[64][LDS];

    const int tid  = threadIdx.x;
    const int warp = tid >> 5;
    const int n0   = blockIdx.x * 64;
    const int m0   = blockIdx.y * 64;

    FragC acc[4];
#pragma unroll
    for (int i = 0; i < 4; i++) wmma::fill_fragment(acc[i], 0.0f);

    for (int kt = 0; kt < DD; kt += 32) {
        // A tile 64x32 (tf32-rounded into smem)
        for (int i = tid; i < 64 * 8; i += 128) {
            int r = i >> 3, c = (i & 7) * 4;
            float4 v = *reinterpret_cast<const float4*>(A + (size_t)(m0 + r) * DD + kt + c);
            As[r][c]     = tf32r(v.x);
            As[r][c + 1] = tf32r(v.y);
            As[r][c + 2] = tf32r(v.z);
            As[r][c + 3] = tf32r(v.w);
        }
        // W tile 32x64
        for (int i = tid; i < 32 * 16; i += 128) {
            int r = i >> 4, c = (i & 15) * 4;
            float4 v = *reinterpret_cast<const float4*>(W + (size_t)(kt + r) * DD + n0 + c);
            Ws[r][c]     = tf32r(v.x);
            Ws[r][c + 1] = tf32r(v.y);
            Ws[r][c + 2] = tf32r(v.z);
            Ws[r][c + 3] = tf32r(v.w);
        }
        __syncthreads();

        FragA a; FragBr b;
#pragma unroll
        for (int kk = 0; kk < 32; kk += 8) {
            wmma::load_matrix_sync(a, &As[warp * 16][kk], 40);
#pragma unroll
            for (int nf = 0; nf < 4; nf++) {
                wmma::load_matrix_sync(b, &Ws[kk][nf * 16], LDS);
                wmma::mma_sync(acc[nf], a, b, acc[nf]);
            }
        }
        __syncthreads();
    }

#pragma unroll
    for (int nf = 0; nf < 4; nf++)
        wmma::store_matrix_sync(&Cs[warp * 16][nf * 16], acc[nf], LDS, wmma::mem_row_major);
    __syncthreads();

    if (head_layout) {
        const int h = n0 >> 6;  // N-tile == exactly one head (64 cols)
        for (int i = tid; i < 64 * 16; i += 128) {
            int r = i >> 4, c = (i & 15) * 4;
            int m = m0 + r;
            int bb = m >> 11, s = m & 2047;
            float4 v;
            v.x = Cs[r][c]     + bias[n0 + c];
            v.y = Cs[r][c + 1] + bias[n0 + c + 1];
            v.z = Cs[r][c + 2] + bias[n0 + c + 2];
            v.w = Cs[r][c + 3] + bias[n0 + c + 3];
            *reinterpret_cast<float4*>(out + (size_t)((bb * HH + h) * SS + s) * DH + c) = v;
        }
    } else {
        for (int i = tid; i < 64 * 16; i += 128) {
            int r = i >> 4, c = (i & 15) * 4;
            float4 v;
            v.x = Cs[r][c]     + bias[n0 + c];
            v.y = Cs[r][c + 1] + bias[n0 + c + 1];
            v.z = Cs[r][c + 2] + bias[n0 + c + 2];
            v.w = Cs[r][c + 3] + bias[n0 + c + 3];
            *reinterpret_cast<float4*>(out + (size_t)(m0 + r) * DD + n0 + c) = v;
        }
    }
}

__global__ void __launch_bounds__(128) proj_qkv_kernel(
    const float* __restrict__ q, const float* __restrict__ k, const float* __restrict__ v,
    const float* __restrict__ Wq, const float* __restrict__ Wk, const float* __restrict__ Wv,
    const float* __restrict__ bq, const float* __restrict__ bk, const float* __restrict__ bv)
{
    const int z = blockIdx.z;
    const float* A    = (z == 0) ? q  : (z == 1) ? k  : v;
    const float* W    = (z == 0) ? Wq : (z == 1) ? Wk : Wv;
    const float* bias = (z == 0) ? bq : (z == 1) ? bk : bv;
    float*       out  = (z == 0) ? g_q : (z == 1) ? g_k : g_v;
    gemm64x64(A, W, bias, out, 1);
}

__global__ void __launch_bounds__(128) proj_out_kernel(
    const float* __restrict__ Wo, const float* __restrict__ bo, float* __restrict__ out)
{
    gemm64x64(g_ctx, Wo, bo, out, 0);
}

// ---------------------------------------------------------------------------
// Flash attention: block = (bh, q-tile of 64 rows). BN = 64 keys/iter.
// Online softmax in fp32 (smem), GEMMs in wmma tf32. 128 threads, 4 warps.
// ---------------------------------------------------------------------------
#define ATTN_SMEM_FLOATS (5 * 64 * LDS + 3 * 64)
#define ATTN_SMEM_BYTES  (ATTN_SMEM_FLOATS * 4)

__global__ void __launch_bounds__(128) attn_kernel(const float* __restrict__ mask)
{
    extern __shared__ float sm[];
    float (*Qs)[LDS] = (float(*)[LDS])(sm);
    float (*Ks)[LDS] = (float(*)[LDS])(sm + 1 * 64 * LDS);
    float (*Vs)[LDS] = (float(*)[LDS])(sm + 2 * 64 * LDS);
    float (*Ss)[LDS] = (float(*)[LDS])(sm + 3 * 64 * LDS);
    float (*Os)[LDS] = (float(*)[LDS])(sm + 4 * 64 * LDS);
    float* m_i   = sm + 5 * 64 * LDS;
    float* l_i   = m_i + 64;
    float* maskS = l_i + 64;

    const int tid  = threadIdx.x;
    const int warp = tid >> 5;
    const int bh = blockIdx.x;          // 0..31  (b*16 + h)
    const int qt = blockIdx.y;          // 0..31  q tile
    const int bb = bh >> 4;
    const int h  = bh & 15;

    const float* Qg = g_q + (size_t)(bh * SS + qt * 64) * DH;
    const float* Kg = g_k + (size_t)bh * SS * DH;
    const float* Vg = g_v + (size_t)bh * SS * DH;

    // Load Q tile (tf32), zero O accumulator
    for (int i = tid; i < 64 * 16; i += 128) {
        int r = i >> 4, c = (i & 15) * 4;
        float4 v = *reinterpret_cast<const float4*>(Qg + r * DH + c);
        Qs[r][c] = tf32r(v.x); Qs[r][c + 1] = tf32r(v.y);
        Qs[r][c + 2] = tf32r(v.z); Qs[r][c + 3] = tf32r(v.w);
        Os[r][c] = 0.f; Os[r][c + 1] = 0.f; Os[r][c + 2] = 0.f; Os[r][c + 3] = 0.f;
    }
    if (tid < 64) { m_i[tid] = -1e30f; l_i[tid] = 0.f; }
    __syncthreads();

    for (int kt0 = 0; kt0 < SS; kt0 += 64) {
        // Load K/V tiles (tf32) + mask strip
        for (int i = tid; i < 64 * 16; i += 128) {
            int r = i >> 4, c = (i & 15) * 4;
            float4 kv = *reinterpret_cast<const float4*>(Kg + (kt0 + r) * DH + c);
            Ks[r][c] = tf32r(kv.x); Ks[r][c + 1] = tf32r(kv.y);
            Ks[r][c + 2] = tf32r(kv.z); Ks[r][c + 3] = tf32r(kv.w);
            float4 vv = *reinterpret_cast<const float4*>(Vg + (kt0 + r) * DH + c);
            Vs[r][c] = tf32r(vv.x); Vs[r][c + 1] = tf32r(vv.y);
            Vs[r][c + 2] = tf32r(vv.z); Vs[r][c + 3] = tf32r(vv.w);
        }
        if (tid < 64) maskS[tid] = mask[bb * SS + kt0 + tid] * (-1e9f);
        __syncthreads();

        // S = Q @ K^T   (64x64, k = DH = 64)
        {
            FragC sAcc[4];
#pragma unroll
            for (int nf = 0; nf < 4; nf++) wmma::fill_fragment(sAcc[nf], 0.0f);
            FragA a; FragBc bK;
#pragma unroll
            for (int kk = 0; kk < DH; kk += 8) {
                wmma::load_matrix_sync(a, &Qs[warp * 16][kk], LDS);
#pragma unroll
                for (int nf = 0; nf < 4; nf++) {
                    wmma::load_matrix_sync(bK, &Ks[nf * 16][kk], LDS);
                    wmma::mma_sync(sAcc[nf], a, bK, sAcc[nf]);
                }
            }
#pragma unroll
            for (int nf = 0; nf < 4; nf++)
                wmma::store_matrix_sync(&Ss[warp * 16][nf * 16], sAcc[nf], LDS, wmma::mem_row_major);
        }
        __syncthreads();

        // Online softmax update (fp32, one thread per row)
        if (tid < 64) {
            const int r = tid;
            float mo = m_i[r];
            float tmax = mo;
#pragma unroll 8
            for (int c = 0; c < 64; c++) {
                float s = Ss[r][c] * 0.125f + maskS[c];
                Ss[r][c] = s;
                tmax = fmaxf(tmax, s);
            }
            float alpha = __expf(mo - tmax);
            float rs = 0.f;
#pragma unroll 8
            for (int c = 0; c < 64; c++) {
                float p = __expf(Ss[r][c] - tmax);
                rs += p;
                Ss[r][c] = tf32r(p);
            }
            l_i[r] = l_i[r] * alpha + rs;
            m_i[r] = tmax;
#pragma unroll 8
            for (int c = 0; c < 64; c++) Os[r][c] *= alpha;
        }
        __syncthreads();

        // O += P @ V   (64x64, k = 64 keys)
        {
            FragC oAcc[4];
#pragma unroll
            for (int nf = 0; nf < 4; nf++)
                wmma::load_matrix_sync(oAcc[nf], &Os[warp * 16][nf * 16], LDS, wmma::mem_row_major);
            FragA a; FragBr bV;
#pragma unroll
            for (int kk = 0; kk < 64; kk += 8) {
                wmma::load_matrix_sync(a, &Ss[warp * 16][kk], LDS);
#pragma unroll
                for (int nf = 0; nf < 4; nf++) {
                    wmma::load_matrix_sync(bV, &Vs[kk][nf * 16], LDS);
                    wmma::mma_sync(oAcc[nf], a, bV, oAcc[nf]);
                }
            }
#pragma unroll
            for (int nf = 0; nf < 4; nf++)
                wmma::store_matrix_sync(&Os[warp * 16][nf * 16], oAcc[nf], LDS, wmma::mem_row_major);
        }
        __syncthreads();
    }

    // Epilogue: normalize and scatter to [B,S,D] ctx
    for (int i = tid; i < 64 * 16; i += 128) {
        int r = i >> 4, c = (i & 15) * 4;
        float inv = 1.0f / l_i[r];
        float4 v;
        v.x = Os[r][c]     * inv;
        v.y = Os[r][c + 1] * inv;
        v.z = Os[r][c + 2] * inv;
        v.w = Os[r][c + 3] * inv;
        *reinterpret_cast<float4*>(g_ctx + (size_t)(bb * SS + qt * 64 + r) * DD + h * DH + c) = v;
    }
}

// ---------------------------------------------------------------------------
extern "C" void kernel_launch(void* const* d_in, const int* in_sizes, int n_in,
                              void* d_out, int out_size)
{
    const float* query = (const float*)d_in[0];
    const float* key   = (const float*)d_in[1];
    const float* value = (const float*)d_in[2];
    const float* mask  = (const float*)d_in[3];
    const float* Wq    = (const float*)d_in[4];
    const float* bq    = (const float*)d_in[5];
    const float* Wk    = (const float*)d_in[6];
    const float* bk    = (const float*)d_in[7];
    const float* Wv    = (const float*)d_in[8];
    const float* bv    = (const float*)d_in[9];
    const float* Wo    = (const float*)d_in[10];
    const float* bo    = (const float*)d_in[11];
    float* out = (float*)d_out;

    cudaFuncSetAttribute(attn_kernel, cudaFuncAttributeMaxDynamicSharedMemorySize, ATTN_SMEM_BYTES);

    // 1) Q/K/V projections into split-head scratch
    proj_qkv_kernel<<<dim3(16, 64, 3), 128>>>(query, key, value, Wq, Wk, Wv, bq, bk, bv);
    // 2) Flash attention -> g_ctx [B,S,D]
    attn_kernel<<<dim3(32, 32), 128, ATTN_SMEM_BYTES>>>(mask);
    // 3) Output projection -> d_out
    proj_out_kernel<<<dim3(16, 64), 128>>>(Wo, bo, out);
}

// round 2
// speedup vs baseline: 1.1125x; 1.1125x over previous
#include <cuda_runtime.h>
#include <mma.h>

using namespace nvcuda;

#define BB   2
#define SS   2048
#define DD   1024
#define HH   16
#define DH   64

// Scratch (allocation-free rule: __device__ globals)
__device__ float g_q[BB * HH * SS * DH];
__device__ float g_k[BB * HH * SS * DH];
__device__ float g_v[BB * HH * SS * DH];
__device__ float g_ctx[BB * SS * DD];

using FragA  = wmma::fragment<wmma::matrix_a, 16, 16, 8, wmma::precision::tf32, wmma::row_major>;
using FragBr = wmma::fragment<wmma::matrix_b, 16, 16, 8, wmma::precision::tf32, wmma::row_major>;
using FragBc = wmma::fragment<wmma::matrix_b, 16, 16, 8, wmma::precision::tf32, wmma::col_major>;
using FragC  = wmma::fragment<wmma::accumulator, 16, 16, 8, float>;

__device__ __forceinline__ float tf32r(float x) { return wmma::__float_to_tf32(x); }

// ---------------------------------------------------------------------------
// Projection GEMM: 128x128 CTA tile, BK=32, 256 threads (8 warps, 4M x 2N),
// register-staged double buffering. out = A[4096,1024] @ W[1024,1024] + bias.
// head_layout=1 -> scatter to [B,H,S,DH].
// ---------------------------------------------------------------------------
#define PBM 128
#define PBN 128
#define PBK 32
#define PLDA 36
#define PLDB 132
#define PLDC 132

#define PROJ_SMEM_FLOATS (2 * PBM * PLDA + 2 * PBK * PLDB)   // 17664
#define PROJ_SMEM_BYTES  (PROJ_SMEM_FLOATS * 4)              // 70656

__device__ __forceinline__ void gemm128(const float* __restrict__ A,
                                        const float* __restrict__ W,
                                        const float* __restrict__ bias,
                                        float* __restrict__ out,
                                        int head_layout)
{
    extern __shared__ float sm[];
    float* As = sm;                       // [2][128*36]
    float* Bs = sm + 2 * PBM * PLDA;      // [2][32*132]
    float* Cs = sm;                       // reuse for epilogue (16896 floats)

    const int tid  = threadIdx.x;
    const int warp = tid >> 5;
    const int wm   = warp >> 1;           // 0..3
    const int wn   = warp & 1;            // 0..1
    const int n0   = blockIdx.x * PBN;
    const int m0   = blockIdx.y * PBM;

    FragC acc[2][4];
#pragma unroll
    for (int mf = 0; mf < 2; mf++)
#pragma unroll
        for (int nf = 0; nf < 4; nf++) wmma::fill_fragment(acc[mf][nf], 0.0f);

    float4 aR[4], bR[4];

    auto loadTiles = [&](int kt) {
#pragma unroll
        for (int t = 0; t < 4; t++) {
            int chunk = tid + t * 256;
            int r = chunk >> 3, c = (chunk & 7) * 4;
            aR[t] = *reinterpret_cast<const float4*>(A + (size_t)(m0 + r) * DD + kt + c);
        }
#pragma unroll
        for (int t = 0; t < 4; t++) {
            int chunk = tid + t * 256;
            int r = chunk >> 5, c = (chunk & 31) * 4;
            bR[t] = *reinterpret_cast<const float4*>(W + (size_t)(kt + r) * DD + n0 + c);
        }
    };
    auto storeTiles = [&](int buf) {
        float* Ab = As + buf * PBM * PLDA;
        float* Bb = Bs + buf * PBK * PLDB;
#pragma unroll
        for (int t = 0; t < 4; t++) {
            int chunk = tid + t * 256;
            int r = chunk >> 3, c = (chunk & 7) * 4;
            float4 v = aR[t];
            v.x = tf32r(v.x); v.y = tf32r(v.y); v.z = tf32r(v.z); v.w = tf32r(v.w);
            *reinterpret_cast<float4*>(Ab + r * PLDA + c) = v;
        }
#pragma unroll
        for (int t = 0; t < 4; t++) {
            int chunk = tid + t * 256;
            int r = chunk >> 5, c = (chunk & 31) * 4;
            float4 v = bR[t];
            v.x = tf32r(v.x); v.y = tf32r(v.y); v.z = tf32r(v.z); v.w = tf32r(v.w);
            *reinterpret_cast<float4*>(Bb + r * PLDB + c) = v;
        }
    };

    loadTiles(0);
    storeTiles(0);
    __syncthreads();

    const int NT = DD / PBK;   // 32
    for (int it = 0; it < NT; it++) {
        const int buf = it & 1;
        if (it + 1 < NT) loadTiles((it + 1) * PBK);   // overlap with compute

        const float* Ab = As + buf * PBM * PLDA;
        const float* Bb = Bs + buf * PBK * PLDB;
        FragA a[2]; FragBr b[4];
#pragma unroll
        for (int kk = 0; kk < PBK; kk += 8) {
#pragma unroll
            for (int mf = 0; mf < 2; mf++)
                wmma::load_matrix_sync(a[mf], Ab + (wm * 32 + mf * 16) * PLDA + kk, PLDA);
#pragma unroll
            for (int nf = 0; nf < 4; nf++)
                wmma::load_matrix_sync(b[nf], Bb + kk * PLDB + wn * 64 + nf * 16, PLDB);
#pragma unroll
            for (int mf = 0; mf < 2; mf++)
#pragma unroll
                for (int nf = 0; nf < 4; nf++)
                    wmma::mma_sync(acc[mf][nf], a[mf], b[nf], acc[mf][nf]);
        }
        __syncthreads();
        if (it + 1 < NT) storeTiles(buf ^ 1);
        __syncthreads();
    }

    // Epilogue: stage to smem, add bias, store coalesced
#pragma unroll
    for (int mf = 0; mf < 2; mf++)
#pragma unroll
        for (int nf = 0; nf < 4; nf++)
            wmma::store_matrix_sync(Cs + (wm * 32 + mf * 16) * PLDC + wn * 64 + nf * 16,
                                    acc[mf][nf], PLDC, wmma::mem_row_major);
    __syncthreads();

#pragma unroll
    for (int t = 0; t < 16; t++) {
        int chunk = tid + t * 256;
        int r = chunk >> 5, c = (chunk & 31) * 4;
        float4 v = *reinterpret_cast<const float4*>(Cs + r * PLDC + c);
        float4 bi = *reinterpret_cast<const float4*>(bias + n0 + c);
        v.x += bi.x; v.y += bi.y; v.z += bi.z; v.w += bi.w;
        int m = m0 + r;
        if (head_layout) {
            int h = (n0 + c) >> 6, d = (n0 + c) & 63;
            int bb = m >> 11, s = m & 2047;
            *reinterpret_cast<float4*>(out + (size_t)((bb * HH + h) * SS + s) * DH + d) = v;
        } else {
            *reinterpret_cast<float4*>(out + (size_t)m * DD + n0 + c) = v;
        }
    }
}

__global__ void __launch_bounds__(256) proj_qkv_kernel(
    const float* __restrict__ q, const float* __restrict__ k, const float* __restrict__ v,
    const float* __restrict__ Wq, const float* __restrict__ Wk, const float* __restrict__ Wv,
    const float* __restrict__ bq, const float* __restrict__ bk, const float* __restrict__ bv)
{
    const int z = blockIdx.z;
    const float* A    = (z == 0) ? q  : (z == 1) ? k  : v;
    const float* W    = (z == 0) ? Wq : (z == 1) ? Wk : Wv;
    const float* bias = (z == 0) ? bq : (z == 1) ? bk : bv;
    float*       out  = (z == 0) ? g_q : (z == 1) ? g_k : g_v;
    gemm128(A, W, bias, out, 1);
}

__global__ void __launch_bounds__(256) proj_out_kernel(
    const float* __restrict__ Wo, const float* __restrict__ bo, float* __restrict__ out)
{
    gemm128(g_ctx, Wo, bo, out, 0);
}

// ---------------------------------------------------------------------------
// Flash attention: BM=128 q rows per CTA, BN=64 keys/iter, 256 threads
// (8 warps, 4M x 2N, warp tile 32x32). Softmax: 2 threads per row.
// ---------------------------------------------------------------------------
#define ALD 68
#define ATTN_SMEM_FLOATS (ALD * (128 + 64 + 64 + 128 + 128) + 128 + 128 + 64)  // 35136
#define ATTN_SMEM_BYTES  (ATTN_SMEM_FLOATS * 4)                                // 140544

__global__ void __launch_bounds__(256) attn_kernel(const float* __restrict__ mask)
{
    extern __shared__ float sm[];
    float* Qs    = sm;                    // 128 x ALD
    float* Ks    = Qs + 128 * ALD;        // 64 x ALD
    float* Vs    = Ks + 64 * ALD;         // 64 x ALD
    float* Ss    = Vs + 64 * ALD;         // 128 x ALD
    float* Os    = Ss + 128 * ALD;        // 128 x ALD
    float* m_i   = Os + 128 * ALD;        // 128
    float* l_i   = m_i + 128;             // 128
    float* maskS = l_i + 128;             // 64

    const int tid  = threadIdx.x;
    const int warp = tid >> 5;
    const int wm   = warp >> 1;           // 0..3 (32-row strip)
    const int wn   = warp & 1;            // 0..1 (32-col strip)
    const int bh   = blockIdx.x;          // b*16 + h
    const int qt   = blockIdx.y;          // 0..15
    const int bb   = bh >> 4;
    const int h    = bh & 15;

    const float* Qg = g_q + (size_t)(bh * SS + qt * 128) * DH;
    const float* Kg = g_k + (size_t)bh * SS * DH;
    const float* Vg = g_v + (size_t)bh * SS * DH;

    // Load Q tile (tf32) and zero O accumulator
#pragma unroll
    for (int t = 0; t < 8; t++) {
        int chunk = tid + t * 256;
        int r = chunk >> 4, c = (chunk & 15) * 4;
        float4 v = *reinterpret_cast<const float4*>(Qg + r * DH + c);
        v.x = tf32r(v.x); v.y = tf32r(v.y); v.z = tf32r(v.z); v.w = tf32r(v.w);
        *reinterpret_cast<float4*>(Qs + r * ALD + c) = v;
        *reinterpret_cast<float4*>(Os + r * ALD + c) = make_float4(0.f, 0.f, 0.f, 0.f);
    }
    if (tid < 128) { m_i[tid] = -1e30f; l_i[tid] = 0.f; }
    __syncthreads();

    for (int kt0 = 0; kt0 < SS; kt0 += 64) {
        // Load K/V tiles + mask strip
#pragma unroll
        for (int t = 0; t < 4; t++) {
            int chunk = tid + t * 256;
            int r = chunk >> 4, c = (chunk & 15) * 4;
            float4 kv = *reinterpret_cast<const float4*>(Kg + (kt0 + r) * DH + c);
            kv.x = tf32r(kv.x); kv.y = tf32r(kv.y); kv.z = tf32r(kv.z); kv.w = tf32r(kv.w);
            *reinterpret_cast<float4*>(Ks + r * ALD + c) = kv;
            float4 vv = *reinterpret_cast<const float4*>(Vg + (kt0 + r) * DH + c);
            vv.x = tf32r(vv.x); vv.y = tf32r(vv.y); vv.z = tf32r(vv.z); vv.w = tf32r(vv.w);
            *reinterpret_cast<float4*>(Vs + r * ALD + c) = vv;
        }
        if (tid < 64) maskS[tid] = mask[bb * SS + kt0 + tid] * (-1e9f);
        __syncthreads();

        // S = Q @ K^T  (128x64, k = DH = 64), warp tile 32x32
        {
            FragC s[2][2];
#pragma unroll
            for (int mf = 0; mf < 2; mf++)
#pragma unroll
                for (int nf = 0; nf < 2; nf++) wmma::fill_fragment(s[mf][nf], 0.0f);
            FragA a[2]; FragBc b[2];
#pragma unroll
            for (int kk = 0; kk < DH; kk += 8) {
#pragma unroll
                for (int mf = 0; mf < 2; mf++)
                    wmma::load_matrix_sync(a[mf], Qs + (wm * 32 + mf * 16) * ALD + kk, ALD);
#pragma unroll
                for (int nf = 0; nf < 2; nf++)
                    wmma::load_matrix_sync(b[nf], Ks + (wn * 32 + nf * 16) * ALD + kk, ALD);
#pragma unroll
                for (int mf = 0; mf < 2; mf++)
#pragma unroll
                    for (int nf = 0; nf < 2; nf++)
                        wmma::mma_sync(s[mf][nf], a[mf], b[nf], s[mf][nf]);
            }
#pragma unroll
            for (int mf = 0; mf < 2; mf++)
#pragma unroll
                for (int nf = 0; nf < 2; nf++)
                    wmma::store_matrix_sync(Ss + (wm * 32 + mf * 16) * ALD + wn * 32 + nf * 16,
                                            s[mf][nf], ALD, wmma::mem_row_major);
        }
        __syncthreads();

        // Online softmax: 2 threads per row (32-col strips), shfl combine
        {
            const int r  = tid >> 1;
            const int hh = tid & 1;
            const int cb = hh * 32;
            float* row = Ss + r * ALD + cb;
            const float mo = m_i[r];
            float mx = -1e30f;
#pragma unroll
            for (int c = 0; c < 32; c++) {
                float s = row[c] * 0.125f + maskS[cb + c];
                row[c] = s;
                mx = fmaxf(mx, s);
            }
            mx = fmaxf(mx, __shfl_xor_sync(0xffffffffu, mx, 1));
            mx = fmaxf(mx, mo);
            const float alpha = __expf(mo - mx);
            float sum = 0.f;
#pragma unroll
            for (int c = 0; c < 32; c++) {
                float p = __expf(row[c] - mx);
                sum += p;
                row[c] = tf32r(p);
            }
            sum += __shfl_xor_sync(0xffffffffu, sum, 1);
            if (hh == 0) { m_i[r] = mx; l_i[r] = l_i[r] * alpha + sum; }
            float* orow = Os + r * ALD + cb;
#pragma unroll
            for (int c = 0; c < 32; c++) orow[c] *= alpha;
        }
        __syncthreads();

        // O += P @ V  (128x64, k = 64), warp tile 32x32
        {
            FragC o[2][2];
#pragma unroll
            for (int mf = 0; mf < 2; mf++)
#pragma unroll
                for (int nf = 0; nf < 2; nf++)
                    wmma::load_matrix_sync(o[mf][nf],
                        Os + (wm * 32 + mf * 16) * ALD + wn * 32 + nf * 16, ALD,
                        wmma::mem_row_major);
            FragA a[2]; FragBr b[2];
#pragma unroll
            for (int kk = 0; kk < 64; kk += 8) {
#pragma unroll
                for (int mf = 0; mf < 2; mf++)
                    wmma::load_matrix_sync(a[mf], Ss + (wm * 32 + mf * 16) * ALD + kk, ALD);
#pragma unroll
                for (int nf = 0; nf < 2; nf++)
                    wmma::load_matrix_sync(b[nf], Vs + kk * ALD + wn * 32 + nf * 16, ALD);
#pragma unroll
                for (int mf = 0; mf < 2; mf++)
#pragma unroll
                    for (int nf = 0; nf < 2; nf++)
                        wmma::mma_sync(o[mf][nf], a[mf], b[nf], o[mf][nf]);
            }
#pragma unroll
            for (int mf = 0; mf < 2; mf++)
#pragma unroll
                for (int nf = 0; nf < 2; nf++)
                    wmma::store_matrix_sync(Os + (wm * 32 + mf * 16) * ALD + wn * 32 + nf * 16,
                                            o[mf][nf], ALD, wmma::mem_row_major);
        }
        __syncthreads();
    }

    // Epilogue: normalize, scatter to [B,S,D] ctx
#pragma unroll
    for (int t = 0; t < 8; t++) {
        int chunk = tid + t * 256;
        int r = chunk >> 4, c = (chunk & 15) * 4;
        float inv = 1.0f / l_i[r];
        float4 v = *reinterpret_cast<const float4*>(Os + r * ALD + c);
        v.x *= inv; v.y *= inv; v.z *= inv; v.w *= inv;
        *reinterpret_cast<float4*>(
            g_ctx + (size_t)(bb * SS + qt * 128 + r) * DD + h * DH + c) = v;
    }
}

// ---------------------------------------------------------------------------
extern "C" void kernel_launch(void* const* d_in, const int* in_sizes, int n_in,
                              void* d_out, int out_size)
{
    const float* query = (const float*)d_in[0];
    const float* key   = (const float*)d_in[1];
    const float* value = (const float*)d_in[2];
    const float* mask  = (const float*)d_in[3];
    const float* Wq    = (const float*)d_in[4];
    const float* bq    = (const float*)d_in[5];
    const float* Wk    = (const float*)d_in[6];
    const float* bk    = (const float*)d_in[7];
    const float* Wv    = (const float*)d_in[8];
    const float* bv    = (const float*)d_in[9];
    const float* Wo    = (const float*)d_in[10];
    const float* bo    = (const float*)d_in[11];
    float* out = (float*)d_out;

    static int configured = 0;
    if (!configured) {
        cudaFuncSetAttribute(proj_qkv_kernel, cudaFuncAttributeMaxDynamicSharedMemorySize, PROJ_SMEM_BYTES);
        cudaFuncSetAttribute(proj_out_kernel, cudaFuncAttributeMaxDynamicSharedMemorySize, PROJ_SMEM_BYTES);
        cudaFuncSetAttribute(attn_kernel,     cudaFuncAttributeMaxDynamicSharedMemorySize, ATTN_SMEM_BYTES);
        configured = 1;
    }

    // 1) Q/K/V projections into split-head scratch
    proj_qkv_kernel<<<dim3(8, 32, 3), 256, PROJ_SMEM_BYTES>>>(query, key, value, Wq, Wk, Wv, bq, bk, bv);
    // 2) Flash attention -> g_ctx [B,S,D]
    attn_kernel<<<dim3(32, 16), 256, ATTN_SMEM_BYTES>>>(mask);
    // 3) Output projection -> d_out
    proj_out_kernel<<<dim3(8, 32), 256, PROJ_SMEM_BYTES>>>(Wo, bo, out);
}